// round 1
// baseline (speedup 1.0000x reference)
#include <cuda_runtime.h>
#include <cuda_bf16.h>
#include <math.h>

// Problem constants
#define NN    20000
#define EE    320000
#define ETOT  340000   // EE + NN self loops
#define TT    10
#define BB    4096
#define EMB   128
#define HEADS 4
#define HC    512      // HEADS*EMB
#define LAYERS 2
#define FLATK 2560     // TT * 2 * EMB

// ---------------- device scratch (no allocation allowed) ----------------
__device__ float g_h [NN * HC];        // GAT linear output [N,512]
__device__ float g_y [NN * HC];        // aggregated output [N,512]
__device__ float g_x [NN * EMB];       // layer output [N,128]
__device__ float g_s [NN * 8];         // per-node attention scores: [n][0..3]=src,[4..7]=dst
__device__ int   g_rowptr[TT * (NN + 1)];
__device__ int   g_wptr  [NN + 1];
__device__ int   g_csr   [TT * ETOT];  // src index per CSR slot (sorted by dst)
__device__ int   g_deg   [NN];
__device__ float g_flat  [BB * FLATK];
__device__ float g_h1    [BB * EMB];

// ---------------- CSR build ----------------
__global__ void init_deg() {
    int i = blockIdx.x * blockDim.x + threadIdx.x;
    if (i < NN) g_deg[i] = 1;  // self loop
}

__global__ void count_deg(const int* __restrict__ dst) {
    int e = blockIdx.x * blockDim.x + threadIdx.x;
    if (e < EE) atomicAdd(&g_deg[dst[e]], 1);
}

__global__ void scan_deg(int* __restrict__ rowptr) {
    __shared__ int buf[1024];
    __shared__ int carry;
    int tid = threadIdx.x;
    if (tid == 0) { carry = 0; rowptr[0] = 0; g_wptr[0] = 0; }
    __syncthreads();
    for (int base = 0; base < NN; base += 1024) {
        int v = (base + tid < NN) ? g_deg[base + tid] : 0;
        buf[tid] = v;
        __syncthreads();
        for (int off = 1; off < 1024; off <<= 1) {
            int t = (tid >= off) ? buf[tid - off] : 0;
            __syncthreads();
            buf[tid] += t;
            __syncthreads();
        }
        int c = carry;
        if (base + tid < NN) {
            rowptr[base + tid + 1] = c + buf[tid];
            g_wptr[base + tid + 1] = c + buf[tid];
        }
        __syncthreads();
        if (tid == 0) carry = c + buf[1023];
        __syncthreads();
    }
}

__global__ void scatter_edges(const int* __restrict__ src, const int* __restrict__ dst,
                              int* __restrict__ csr) {
    int e = blockIdx.x * blockDim.x + threadIdx.x;
    if (e < EE) {
        int pos = atomicAdd(&g_wptr[dst[e]], 1);
        csr[pos] = src[e];
    }
}

__global__ void scatter_self(int* __restrict__ csr) {
    int n = blockIdx.x * blockDim.x + threadIdx.x;
    if (n < NN) {
        int pos = atomicAdd(&g_wptr[n], 1);
        csr[pos] = n;
    }
}

// ---------------- SGEMM: C = A @ Bw^T (+bias, +relu) ----------------
// A [M,K] row-major, Bw [N,K] row-major, C [M,N] row-major.
// BM=BN=128, BK=16, TM=TN=8, 256 threads. K % 16 == 0, N % 128 == 0 required.
__global__ void sgemm_abt(const float* __restrict__ A, const float* __restrict__ Bw,
                          const float* __restrict__ bias, float* __restrict__ C,
                          int M, int N, int K, int relu) {
    const int BM = 128, BN = 128, BK = 16, TM = 8, TN = 8;
    __shared__ float As[BK][BM];
    __shared__ float Bs[BK][BN];
    int bm = blockIdx.y * BM, bn = blockIdx.x * BN;
    int tid = threadIdx.x;
    int tr = tid / (BN / TN);     // 0..15
    int tc = tid % (BN / TN);     // 0..15

    float acc[TM][TN];
#pragma unroll
    for (int i = 0; i < TM; i++)
#pragma unroll
        for (int j = 0; j < TN; j++) acc[i][j] = 0.f;

    for (int k0 = 0; k0 < K; k0 += BK) {
#pragma unroll
        for (int i = 0; i < 2; i++) {
            int idx = tid + i * 256;       // 0..511 (float4 index)
            int row = idx >> 2;
            int c4 = (idx & 3) * 4;
            int gr = bm + row;
            float4 v = make_float4(0.f, 0.f, 0.f, 0.f);
            if (gr < M) v = *(const float4*)(A + (size_t)gr * K + k0 + c4);
            As[c4 + 0][row] = v.x; As[c4 + 1][row] = v.y;
            As[c4 + 2][row] = v.z; As[c4 + 3][row] = v.w;
        }
#pragma unroll
        for (int i = 0; i < 2; i++) {
            int idx = tid + i * 256;
            int row = idx >> 2;
            int c4 = (idx & 3) * 4;
            float4 v = *(const float4*)(Bw + (size_t)(bn + row) * K + k0 + c4);
            Bs[c4 + 0][row] = v.x; Bs[c4 + 1][row] = v.y;
            Bs[c4 + 2][row] = v.z; Bs[c4 + 3][row] = v.w;
        }
        __syncthreads();
#pragma unroll
        for (int k = 0; k < BK; k++) {
            float ar[TM], br[TN];
#pragma unroll
            for (int i = 0; i < TM; i++) ar[i] = As[k][tr * TM + i];
#pragma unroll
            for (int j = 0; j < TN; j++) br[j] = Bs[k][tc * TN + j];
#pragma unroll
            for (int i = 0; i < TM; i++)
#pragma unroll
                for (int j = 0; j < TN; j++) acc[i][j] += ar[i] * br[j];
        }
        __syncthreads();
    }
#pragma unroll
    for (int i = 0; i < TM; i++) {
        int gr = bm + tr * TM + i;
        if (gr >= M) continue;
#pragma unroll
        for (int j = 0; j < TN; j++) {
            int gc = bn + tc * TN + j;
            float v = acc[i][j];
            if (bias) v += bias[gc];
            if (relu) v = fmaxf(v, 0.f);
            C[(size_t)gr * N + gc] = v;
        }
    }
}

// ---------------- per-node attention scores ----------------
// s[n][h]   = sum_c h[n,h,c]*a_s[h,c]
// s[n][4+h] = sum_c h[n,h,c]*a_d[h,c]
// One warp per node, 8 nodes per 256-thread block.
__global__ void attn_scores(const float* __restrict__ h, const float* __restrict__ as_,
                            const float* __restrict__ ad_) {
    int gwarp = (blockIdx.x * blockDim.x + threadIdx.x) >> 5;
    int lane = threadIdx.x & 31;
    if (gwarp >= NN) return;
    const float* hp = h + (size_t)gwarp * HC;
    float aS[4] = {0.f, 0.f, 0.f, 0.f};
    float aD[4] = {0.f, 0.f, 0.f, 0.f};
#pragma unroll
    for (int i = 0; i < 16; i++) {
        int c = lane + 32 * i;       // enumerates all 512 = h*128 + cm
        float v = hp[c];
        int hh = i >> 2;
        aS[hh] += v * as_[c];
        aD[hh] += v * ad_[c];
    }
#pragma unroll
    for (int hh = 0; hh < 4; hh++) {
#pragma unroll
        for (int off = 16; off; off >>= 1) {
            aS[hh] += __shfl_xor_sync(0xffffffffu, aS[hh], off);
            aD[hh] += __shfl_xor_sync(0xffffffffu, aD[hh], off);
        }
    }
    if (lane == 0) {
        float* sp = g_s + gwarp * 8;
        sp[0] = aS[0]; sp[1] = aS[1]; sp[2] = aS[2]; sp[3] = aS[3];
        sp[4] = aD[0]; sp[5] = aD[1]; sp[6] = aD[2]; sp[7] = aD[3];
    }
}

// ---------------- GAT segment softmax + aggregation ----------------
// One 128-thread block per destination node; warp w handles head w.
__global__ void gat_aggregate(const float* __restrict__ h,
                              const int* __restrict__ rowptr, const int* __restrict__ csr,
                              const float* __restrict__ gbias, float* __restrict__ y) {
    int d = blockIdx.x;
    int tid = threadIdx.x;
    int start = rowptr[d], end = rowptr[d + 1];

    __shared__ float red[128];
    __shared__ float m[4], invsum[4], sdst[4];
    if (tid < 4) sdst[tid] = g_s[d * 8 + 4 + tid];
    __syncthreads();

    // pass 1: per-head max logit
    float mx[4] = {-1e30f, -1e30f, -1e30f, -1e30f};
    for (int e = start + tid; e < end; e += 128) {
        int sidx = csr[e];
#pragma unroll
        for (int hh = 0; hh < 4; hh++) {
            float l = g_s[sidx * 8 + hh] + sdst[hh];
            l = l > 0.f ? l : 0.2f * l;
            mx[hh] = fmaxf(mx[hh], l);
        }
    }
#pragma unroll
    for (int hh = 0; hh < 4; hh++) {
        red[tid] = mx[hh];
        __syncthreads();
        for (int off = 64; off; off >>= 1) {
            if (tid < off) red[tid] = fmaxf(red[tid], red[tid + off]);
            __syncthreads();
        }
        if (tid == 0) m[hh] = red[0];
        __syncthreads();
    }

    // pass 2: per-head sum of exp
    float sm[4] = {0.f, 0.f, 0.f, 0.f};
    for (int e = start + tid; e < end; e += 128) {
        int sidx = csr[e];
#pragma unroll
        for (int hh = 0; hh < 4; hh++) {
            float l = g_s[sidx * 8 + hh] + sdst[hh];
            l = l > 0.f ? l : 0.2f * l;
            sm[hh] += expf(l - m[hh]);
        }
    }
#pragma unroll
    for (int hh = 0; hh < 4; hh++) {
        red[tid] = sm[hh];
        __syncthreads();
        for (int off = 64; off; off >>= 1) {
            if (tid < off) red[tid] += red[tid + off];
            __syncthreads();
        }
        if (tid == 0) invsum[hh] = 1.f / red[0];
        __syncthreads();
    }

    // pass 3: weighted aggregation; warp per head, lane covers 4 channels
    int head = tid >> 5, lane = tid & 31;
    float mh = m[head], inv = invsum[head], sd = sdst[head];
    float acc0 = 0.f, acc1 = 0.f, acc2 = 0.f, acc3 = 0.f;
    for (int e = start; e < end; e++) {
        int sidx = csr[e];
        float l = g_s[sidx * 8 + head] + sd;      // uniform-address broadcast load
        l = l > 0.f ? l : 0.2f * l;
        float alpha = expf(l - mh) * inv;         // whole-warp MUFU == 1-lane cost
        const float* hp = h + (size_t)sidx * HC + head * EMB + lane;
        acc0 += alpha * hp[0];
        acc1 += alpha * hp[32];
        acc2 += alpha * hp[64];
        acc3 += alpha * hp[96];
    }
    int ob = d * HC + head * EMB + lane;
    int bb = head * EMB + lane;
    y[ob +  0] = acc0 + gbias[bb +  0];
    y[ob + 32] = acc1 + gbias[bb + 32];
    y[ob + 64] = acc2 + gbias[bb + 64];
    y[ob + 96] = acc3 + gbias[bb + 96];
}

// ---------------- gather clf rows into reversed-time flat layout ----------------
__global__ void gather_clf(const float* __restrict__ x, const int* __restrict__ clf, int slot) {
    int idx = blockIdx.x * blockDim.x + threadIdx.x;  // BB*128
    if (idx >= BB * EMB) return;
    int b = idx >> 7, c = idx & 127;
    g_flat[(size_t)b * FLATK + slot + c] = x[(size_t)clf[b] * EMB + c];
}

// ---------------- final fc2 ----------------
__global__ void fc2_kernel(const float* __restrict__ W, const float* __restrict__ bias,
                           float* __restrict__ out) {
    int idx = blockIdx.x * blockDim.x + threadIdx.x;  // BB*2
    if (idx >= BB * 2) return;
    int b = idx >> 1, o = idx & 1;
    const float* hp = g_h1 + (size_t)b * EMB;
    const float* wp = W + o * EMB;
    float acc = bias[o];
#pragma unroll 4
    for (int j = 0; j < EMB; j++) acc += hp[j] * wp[j];
    out[idx] = fmaxf(acc, 0.f);
}

// ---------------- host ----------------
extern "C" void kernel_launch(void* const* d_in, const int* in_sizes, int n_in,
                              void* d_out, int out_size) {
    (void)in_sizes; (void)n_in; (void)out_size;
    const float* emb   = (const float*)d_in[0];
    const int*   edges = (const int*)d_in[1];
    const int*   clf   = (const int*)d_in[5];
    const float* gatW[2] = {(const float*)d_in[6],  (const float*)d_in[12]};
    const float* gas[2]  = {(const float*)d_in[7],  (const float*)d_in[13]};
    const float* gad[2]  = {(const float*)d_in[8],  (const float*)d_in[14]};
    const float* gb[2]   = {(const float*)d_in[9],  (const float*)d_in[15]};
    const float* lW[2]   = {(const float*)d_in[10], (const float*)d_in[16]};
    const float* lb[2]   = {(const float*)d_in[11], (const float*)d_in[17]};
    const float* fc1W = (const float*)d_in[18];
    const float* fc1b = (const float*)d_in[19];
    const float* fc2W = (const float*)d_in[20];
    const float* fc2b = (const float*)d_in[21];

    float *h_, *y_, *x_, *flat_, *h1_;
    int *rowptr_, *csr_;
    cudaGetSymbolAddress((void**)&h_,      g_h);
    cudaGetSymbolAddress((void**)&y_,      g_y);
    cudaGetSymbolAddress((void**)&x_,      g_x);
    cudaGetSymbolAddress((void**)&flat_,   g_flat);
    cudaGetSymbolAddress((void**)&h1_,     g_h1);
    cudaGetSymbolAddress((void**)&rowptr_, g_rowptr);
    cudaGetSymbolAddress((void**)&csr_,    g_csr);

    // build CSR (with self loops) per timestep; shared by both branches and layers
    for (int t = 0; t < TT; t++) {
        const int* src = edges + (size_t)t * 2 * EE;
        const int* dst = src + EE;
        init_deg<<<(NN + 255) / 256, 256>>>();
        count_deg<<<(EE + 255) / 256, 256>>>(dst);
        scan_deg<<<1, 1024>>>(rowptr_ + t * (NN + 1));
        scatter_edges<<<(EE + 255) / 256, 256>>>(src, dst, csr_ + (size_t)t * ETOT);
        scatter_self<<<(NN + 255) / 256, 256>>>(csr_ + (size_t)t * ETOT);
    }

    const int MY = (NN + 127) / 128;  // 157
    for (int br = 0; br < 2; br++) {
        for (int t = 0; t < TT; t++) {
            const float* x_in = emb + (size_t)t * NN * EMB;
            for (int l = 0; l < LAYERS; l++) {
                // h = x @ gatW^T  [N,512]
                sgemm_abt<<<dim3(HC / 128, MY), 256>>>(
                    x_in, gatW[br] + (size_t)l * HC * EMB, nullptr, h_, NN, HC, EMB, 0);
                attn_scores<<<(NN * 32 + 255) / 256, 256>>>(
                    h_, gas[br] + l * HC, gad[br] + l * HC);
                gat_aggregate<<<NN, 128>>>(
                    h_, rowptr_ + t * (NN + 1), csr_ + (size_t)t * ETOT,
                    gb[br] + l * HC, y_);
                // x = relu(y @ lW^T + lb)  [N,128]
                sgemm_abt<<<dim3(EMB / 128, MY), 256>>>(
                    y_, lW[br] + (size_t)l * EMB * HC, lb[br] + l * EMB, x_, NN, EMB, HC, 1);
                x_in = x_;
            }
            gather_clf<<<(BB * EMB + 255) / 256, 256>>>(x_, clf, (TT - 1 - t) * 256 + br * EMB);
        }
    }

    // head MLP
    sgemm_abt<<<dim3(1, BB / 128), 256>>>(flat_, fc1W, fc1b, h1_, BB, EMB, FLATK, 1);
    fc2_kernel<<<(BB * 2 + 255) / 256, 256>>>(fc2W, fc2b, (float*)d_out);
}

// round 3
// speedup vs baseline: 1.4268x; 1.4268x over previous
#include <cuda_runtime.h>
#include <cuda_bf16.h>
#include <math.h>
#include <stdint.h>

// Problem constants
#define NN    20000
#define EE    320000
#define ETOT  340000   // EE + NN self loops
#define TT    10
#define BB    4096
#define EMB   128
#define HEADS 4
#define HC    512      // HEADS*EMB
#define LAYERS 2
#define FLATK 2560     // TT * 2 * EMB

// ---------------- device scratch (no allocation allowed) ----------------
__device__ float g_h [NN * HC];        // GAT linear output [N,512]
__device__ float g_y [NN * HC];        // aggregated output [N,512]
__device__ float g_x [NN * EMB];       // layer output [N,128]
__device__ float g_s [NN * 8];         // per-node attention scores
__device__ int   g_rowptr[TT * (NN + 1)];
__device__ int   g_wptr  [NN + 1];
__device__ int   g_csr   [TT * ETOT];
__device__ int   g_deg   [NN];
__device__ float g_flat  [BB * FLATK];
__device__ float g_h1    [BB * EMB];

// ============================================================================
// bf16x3 GEMM via mma.sync (HMMA): C = A @ W^T (+bias, +relu)
// A [M,K] f32 row-major, W [Ntot,K] f32 row-major, C [M,Ntot] f32.
// Requires K % 32 == 0, Ntot % 128 == 0. M arbitrary.
// Block = 256 threads (8 warps, 2x4), tile BM=128, BN=128, BK=32.
// Error model: computes hi*hi + hi*lo + lo*hi; drops lo*lo (~1.5e-5 rel).
// ============================================================================
#define BKP 40   // smem row stride in bf16 (32 + 8 pad; conflict-free frag reads)

__device__ __forceinline__ void mma16816(float* c, uint32_t a0, uint32_t a1,
                                         uint32_t a2, uint32_t a3,
                                         uint32_t b0, uint32_t b1) {
    asm volatile(
        "mma.sync.aligned.m16n8k16.row.col.f32.bf16.bf16.f32 "
        "{%0,%1,%2,%3}, {%4,%5,%6,%7}, {%8,%9}, {%0,%1,%2,%3};"
        : "+f"(c[0]), "+f"(c[1]), "+f"(c[2]), "+f"(c[3])
        : "r"(a0), "r"(a1), "r"(a2), "r"(a3), "r"(b0), "r"(b1));
}

__global__ __launch_bounds__(256, 1)
void gemm_bf16x3(const float* __restrict__ A, const float* __restrict__ W,
                 const float* __restrict__ bias, float* __restrict__ C,
                 int M, int Ntot, int K, int relu)
{
    __shared__ __nv_bfloat16 Ah[128][BKP], Al[128][BKP];
    __shared__ __nv_bfloat16 Bh[128][BKP], Bl[128][BKP];

    const int tid  = threadIdx.x;
    const int warp = tid >> 5;
    const int lane = tid & 31;
    const int g    = lane >> 2;      // 0..7
    const int tg   = lane & 3;       // 0..3
    const int wm   = (warp >> 2) * 64;   // warp row offset in tile
    const int wn   = (warp & 3) * 32;    // warp col offset in tile
    const int bm   = blockIdx.y * 128;
    const int bn   = blockIdx.x * 128;

    float acc[4][4][4];
#pragma unroll
    for (int mi = 0; mi < 4; mi++)
#pragma unroll
        for (int ni = 0; ni < 4; ni++)
#pragma unroll
            for (int q = 0; q < 4; q++) acc[mi][ni][q] = 0.f;

    for (int k0 = 0; k0 < K; k0 += 32) {
        // ---- fill A hi/lo tile (128 x 32) ----
#pragma unroll
        for (int i = 0; i < 8; i++) {
            int p = tid + (i << 8);      // 0..2047 pair index
            int r = p >> 4;              // row 0..127
            int kp = p & 15;             // k-pair 0..15
            float2 v = make_float2(0.f, 0.f);
            int gr = bm + r;
            if (gr < M) v = *(const float2*)(A + (size_t)gr * K + k0 + kp * 2);
            __nv_bfloat16 hx = __float2bfloat16(v.x);
            __nv_bfloat16 hy = __float2bfloat16(v.y);
            __nv_bfloat16 lx = __float2bfloat16(v.x - __bfloat162float(hx));
            __nv_bfloat16 ly = __float2bfloat16(v.y - __bfloat162float(hy));
            *(uint32_t*)&Ah[r][kp * 2] =
                (uint32_t)__bfloat16_as_ushort(hx) | ((uint32_t)__bfloat16_as_ushort(hy) << 16);
            *(uint32_t*)&Al[r][kp * 2] =
                (uint32_t)__bfloat16_as_ushort(lx) | ((uint32_t)__bfloat16_as_ushort(ly) << 16);
        }
        // ---- fill B hi/lo tile (128 x 32) ----
#pragma unroll
        for (int i = 0; i < 8; i++) {
            int p = tid + (i << 8);
            int r = p >> 4;
            int kp = p & 15;
            float2 v = *(const float2*)(W + (size_t)(bn + r) * K + k0 + kp * 2);
            __nv_bfloat16 hx = __float2bfloat16(v.x);
            __nv_bfloat16 hy = __float2bfloat16(v.y);
            __nv_bfloat16 lx = __float2bfloat16(v.x - __bfloat162float(hx));
            __nv_bfloat16 ly = __float2bfloat16(v.y - __bfloat162float(hy));
            *(uint32_t*)&Bh[r][kp * 2] =
                (uint32_t)__bfloat16_as_ushort(hx) | ((uint32_t)__bfloat16_as_ushort(hy) << 16);
            *(uint32_t*)&Bl[r][kp * 2] =
                (uint32_t)__bfloat16_as_ushort(lx) | ((uint32_t)__bfloat16_as_ushort(ly) << 16);
        }
        __syncthreads();

#pragma unroll
        for (int ks = 0; ks < 2; ks++) {
            const int kb = ks * 16;
            uint32_t ah[4][4], al[4][4], bh[4][2], bl[4][2];
#pragma unroll
            for (int mi = 0; mi < 4; mi++) {
                int r = wm + mi * 16;
                ah[mi][0] = *(uint32_t*)&Ah[r + g     ][kb + tg * 2];
                ah[mi][1] = *(uint32_t*)&Ah[r + g + 8 ][kb + tg * 2];
                ah[mi][2] = *(uint32_t*)&Ah[r + g     ][kb + tg * 2 + 8];
                ah[mi][3] = *(uint32_t*)&Ah[r + g + 8 ][kb + tg * 2 + 8];
                al[mi][0] = *(uint32_t*)&Al[r + g     ][kb + tg * 2];
                al[mi][1] = *(uint32_t*)&Al[r + g + 8 ][kb + tg * 2];
                al[mi][2] = *(uint32_t*)&Al[r + g     ][kb + tg * 2 + 8];
                al[mi][3] = *(uint32_t*)&Al[r + g + 8 ][kb + tg * 2 + 8];
            }
#pragma unroll
            for (int ni = 0; ni < 4; ni++) {
                int r = wn + ni * 8 + g;
                bh[ni][0] = *(uint32_t*)&Bh[r][kb + tg * 2];
                bh[ni][1] = *(uint32_t*)&Bh[r][kb + tg * 2 + 8];
                bl[ni][0] = *(uint32_t*)&Bl[r][kb + tg * 2];
                bl[ni][1] = *(uint32_t*)&Bl[r][kb + tg * 2 + 8];
            }
#pragma unroll
            for (int mi = 0; mi < 4; mi++)
#pragma unroll
                for (int ni = 0; ni < 4; ni++) {
                    mma16816(acc[mi][ni], ah[mi][0], ah[mi][1], ah[mi][2], ah[mi][3],
                             bh[ni][0], bh[ni][1]);
                    mma16816(acc[mi][ni], ah[mi][0], ah[mi][1], ah[mi][2], ah[mi][3],
                             bl[ni][0], bl[ni][1]);
                    mma16816(acc[mi][ni], al[mi][0], al[mi][1], al[mi][2], al[mi][3],
                             bh[ni][0], bh[ni][1]);
                }
        }
        __syncthreads();
    }

    // ---- epilogue ----
#pragma unroll
    for (int mi = 0; mi < 4; mi++) {
        int r0 = bm + wm + mi * 16 + g;
        int r1 = r0 + 8;
#pragma unroll
        for (int ni = 0; ni < 4; ni++) {
            int cc = bn + wn + ni * 8 + tg * 2;
            float b0 = 0.f, b1 = 0.f;
            if (bias) { b0 = bias[cc]; b1 = bias[cc + 1]; }
            float2 v0 = make_float2(acc[mi][ni][0] + b0, acc[mi][ni][1] + b1);
            float2 v1 = make_float2(acc[mi][ni][2] + b0, acc[mi][ni][3] + b1);
            if (relu) {
                v0.x = fmaxf(v0.x, 0.f); v0.y = fmaxf(v0.y, 0.f);
                v1.x = fmaxf(v1.x, 0.f); v1.y = fmaxf(v1.y, 0.f);
            }
            if (r0 < M) *(float2*)(C + (size_t)r0 * Ntot + cc) = v0;
            if (r1 < M) *(float2*)(C + (size_t)r1 * Ntot + cc) = v1;
        }
    }
}

// ---------------- CSR build ----------------
__global__ void init_deg() {
    int i = blockIdx.x * blockDim.x + threadIdx.x;
    if (i < NN) g_deg[i] = 1;
}

__global__ void count_deg(const int* __restrict__ dst) {
    int e = blockIdx.x * blockDim.x + threadIdx.x;
    if (e < EE) atomicAdd(&g_deg[dst[e]], 1);
}

__global__ void scan_deg(int* __restrict__ rowptr) {
    __shared__ int buf[1024];
    __shared__ int carry;
    int tid = threadIdx.x;
    if (tid == 0) { carry = 0; rowptr[0] = 0; g_wptr[0] = 0; }
    __syncthreads();
    for (int base = 0; base < NN; base += 1024) {
        int v = (base + tid < NN) ? g_deg[base + tid] : 0;
        buf[tid] = v;
        __syncthreads();
        for (int off = 1; off < 1024; off <<= 1) {
            int t = (tid >= off) ? buf[tid - off] : 0;
            __syncthreads();
            buf[tid] += t;
            __syncthreads();
        }
        int c = carry;
        if (base + tid < NN) {
            rowptr[base + tid + 1] = c + buf[tid];
            g_wptr[base + tid + 1] = c + buf[tid];
        }
        __syncthreads();
        if (tid == 0) carry = c + buf[1023];
        __syncthreads();
    }
}

__global__ void scatter_edges(const int* __restrict__ src, const int* __restrict__ dst,
                              int* __restrict__ csr) {
    int e = blockIdx.x * blockDim.x + threadIdx.x;
    if (e < EE) {
        int pos = atomicAdd(&g_wptr[dst[e]], 1);
        csr[pos] = src[e];
    }
}

__global__ void scatter_self(int* __restrict__ csr) {
    int n = blockIdx.x * blockDim.x + threadIdx.x;
    if (n < NN) {
        int pos = atomicAdd(&g_wptr[n], 1);
        csr[pos] = n;
    }
}

// ---------------- per-node attention scores ----------------
__global__ void attn_scores(const float* __restrict__ h, const float* __restrict__ as_,
                            const float* __restrict__ ad_) {
    int gwarp = (blockIdx.x * blockDim.x + threadIdx.x) >> 5;
    int lane = threadIdx.x & 31;
    if (gwarp >= NN) return;
    const float* hp = h + (size_t)gwarp * HC;
    float aS[4] = {0.f, 0.f, 0.f, 0.f};
    float aD[4] = {0.f, 0.f, 0.f, 0.f};
#pragma unroll
    for (int i = 0; i < 16; i++) {
        int c = lane + 32 * i;
        float v = hp[c];
        int hh = i >> 2;
        aS[hh] += v * as_[c];
        aD[hh] += v * ad_[c];
    }
#pragma unroll
    for (int hh = 0; hh < 4; hh++) {
#pragma unroll
        for (int off = 16; off; off >>= 1) {
            aS[hh] += __shfl_xor_sync(0xffffffffu, aS[hh], off);
            aD[hh] += __shfl_xor_sync(0xffffffffu, aD[hh], off);
        }
    }
    if (lane == 0) {
        float* sp = g_s + gwarp * 8;
        sp[0] = aS[0]; sp[1] = aS[1]; sp[2] = aS[2]; sp[3] = aS[3];
        sp[4] = aD[0]; sp[5] = aD[1]; sp[6] = aD[2]; sp[7] = aD[3];
    }
}

// ---------------- GAT segment softmax + aggregation ----------------
__global__ void gat_aggregate(const float* __restrict__ h,
                              const int* __restrict__ rowptr, const int* __restrict__ csr,
                              const float* __restrict__ gbias, float* __restrict__ y) {
    int d = blockIdx.x;
    int tid = threadIdx.x;
    int start = rowptr[d], end = rowptr[d + 1];

    __shared__ float red[128];
    __shared__ float m[4], invsum[4], sdst[4];
    if (tid < 4) sdst[tid] = g_s[d * 8 + 4 + tid];
    __syncthreads();

    float mx[4] = {-1e30f, -1e30f, -1e30f, -1e30f};
    for (int e = start + tid; e < end; e += 128) {
        int sidx = csr[e];
#pragma unroll
        for (int hh = 0; hh < 4; hh++) {
            float l = g_s[sidx * 8 + hh] + sdst[hh];
            l = l > 0.f ? l : 0.2f * l;
            mx[hh] = fmaxf(mx[hh], l);
        }
    }
#pragma unroll
    for (int hh = 0; hh < 4; hh++) {
        red[tid] = mx[hh];
        __syncthreads();
        for (int off = 64; off; off >>= 1) {
            if (tid < off) red[tid] = fmaxf(red[tid], red[tid + off]);
            __syncthreads();
        }
        if (tid == 0) m[hh] = red[0];
        __syncthreads();
    }

    float sm[4] = {0.f, 0.f, 0.f, 0.f};
    for (int e = start + tid; e < end; e += 128) {
        int sidx = csr[e];
#pragma unroll
        for (int hh = 0; hh < 4; hh++) {
            float l = g_s[sidx * 8 + hh] + sdst[hh];
            l = l > 0.f ? l : 0.2f * l;
            sm[hh] += expf(l - m[hh]);
        }
    }
#pragma unroll
    for (int hh = 0; hh < 4; hh++) {
        red[tid] = sm[hh];
        __syncthreads();
        for (int off = 64; off; off >>= 1) {
            if (tid < off) red[tid] += red[tid + off];
            __syncthreads();
        }
        if (tid == 0) invsum[hh] = 1.f / red[0];
        __syncthreads();
    }

    int head = tid >> 5, lane = tid & 31;
    float mh = m[head], inv = invsum[head], sd = sdst[head];
    float acc0 = 0.f, acc1 = 0.f, acc2 = 0.f, acc3 = 0.f;
    for (int e = start; e < end; e++) {
        int sidx = csr[e];
        float l = g_s[sidx * 8 + head] + sd;
        l = l > 0.f ? l : 0.2f * l;
        float alpha = expf(l - mh) * inv;
        const float* hp = h + (size_t)sidx * HC + head * EMB + lane;
        acc0 += alpha * hp[0];
        acc1 += alpha * hp[32];
        acc2 += alpha * hp[64];
        acc3 += alpha * hp[96];
    }
    int ob = d * HC + head * EMB + lane;
    int bb = head * EMB + lane;
    y[ob +  0] = acc0 + gbias[bb +  0];
    y[ob + 32] = acc1 + gbias[bb + 32];
    y[ob + 64] = acc2 + gbias[bb + 64];
    y[ob + 96] = acc3 + gbias[bb + 96];
}

// ---------------- gather clf rows into reversed-time flat layout ----------------
__global__ void gather_clf(const float* __restrict__ x, const int* __restrict__ clf, int slot) {
    int idx = blockIdx.x * blockDim.x + threadIdx.x;
    if (idx >= BB * EMB) return;
    int b = idx >> 7, c = idx & 127;
    g_flat[(size_t)b * FLATK + slot + c] = x[(size_t)clf[b] * EMB + c];
}

// ---------------- final fc2 ----------------
__global__ void fc2_kernel(const float* __restrict__ W, const float* __restrict__ bias,
                           float* __restrict__ out) {
    int idx = blockIdx.x * blockDim.x + threadIdx.x;
    if (idx >= BB * 2) return;
    int b = idx >> 1, o = idx & 1;
    const float* hp = g_h1 + (size_t)b * EMB;
    const float* wp = W + o * EMB;
    float acc = bias[o];
#pragma unroll 4
    for (int j = 0; j < EMB; j++) acc += hp[j] * wp[j];
    out[idx] = fmaxf(acc, 0.f);
}

// ---------------- host ----------------
extern "C" void kernel_launch(void* const* d_in, const int* in_sizes, int n_in,
                              void* d_out, int out_size) {
    (void)in_sizes; (void)n_in; (void)out_size;
    const float* emb   = (const float*)d_in[0];
    const int*   edges = (const int*)d_in[1];
    const int*   clf   = (const int*)d_in[5];
    const float* gatW[2] = {(const float*)d_in[6],  (const float*)d_in[12]};
    const float* gas[2]  = {(const float*)d_in[7],  (const float*)d_in[13]};
    const float* gad[2]  = {(const float*)d_in[8],  (const float*)d_in[14]};
    const float* gb[2]   = {(const float*)d_in[9],  (const float*)d_in[15]};
    const float* lW[2]   = {(const float*)d_in[10], (const float*)d_in[16]};
    const float* lb[2]   = {(const float*)d_in[11], (const float*)d_in[17]};
    const float* fc1W = (const float*)d_in[18];
    const float* fc1b = (const float*)d_in[19];
    const float* fc2W = (const float*)d_in[20];
    const float* fc2b = (const float*)d_in[21];

    float *h_, *y_, *x_, *flat_, *h1_;
    int *rowptr_, *csr_;
    cudaGetSymbolAddress((void**)&h_,      g_h);
    cudaGetSymbolAddress((void**)&y_,      g_y);
    cudaGetSymbolAddress((void**)&x_,      g_x);
    cudaGetSymbolAddress((void**)&flat_,   g_flat);
    cudaGetSymbolAddress((void**)&h1_,     g_h1);
    cudaGetSymbolAddress((void**)&rowptr_, g_rowptr);
    cudaGetSymbolAddress((void**)&csr_,    g_csr);

    // build CSR (with self loops) per timestep
    for (int t = 0; t < TT; t++) {
        const int* src = edges + (size_t)t * 2 * EE;
        const int* dst = src + EE;
        init_deg<<<(NN + 255) / 256, 256>>>();
        count_deg<<<(EE + 255) / 256, 256>>>(dst);
        scan_deg<<<1, 1024>>>(rowptr_ + t * (NN + 1));
        scatter_edges<<<(EE + 255) / 256, 256>>>(src, dst, csr_ + (size_t)t * ETOT);
        scatter_self<<<(NN + 255) / 256, 256>>>(csr_ + (size_t)t * ETOT);
    }

    const int MY = (NN + 127) / 128;  // 157
    for (int br = 0; br < 2; br++) {
        for (int t = 0; t < TT; t++) {
            const float* x_in = emb + (size_t)t * NN * EMB;
            for (int l = 0; l < LAYERS; l++) {
                // h = x @ gatW^T  [N,512]
                gemm_bf16x3<<<dim3(HC / 128, MY), 256>>>(
                    x_in, gatW[br] + (size_t)l * HC * EMB, nullptr, h_, NN, HC, EMB, 0);
                attn_scores<<<(NN * 32 + 255) / 256, 256>>>(
                    h_, gas[br] + l * HC, gad[br] + l * HC);
                gat_aggregate<<<NN, 128>>>(
                    h_, rowptr_ + t * (NN + 1), csr_ + (size_t)t * ETOT,
                    gb[br] + l * HC, y_);
                // x = relu(y @ lW^T + lb)  [N,128]
                gemm_bf16x3<<<dim3(EMB / 128, MY), 256>>>(
                    y_, lW[br] + (size_t)l * EMB * HC, lb[br] + l * EMB, x_, NN, EMB, HC, 1);
                x_in = x_;
            }
            gather_clf<<<(BB * EMB + 255) / 256, 256>>>(x_, clf, (TT - 1 - t) * 256 + br * EMB);
        }
    }

    // head MLP
    gemm_bf16x3<<<dim3(1, BB / 128), 256>>>(flat_, fc1W, fc1b, h1_, BB, EMB, FLATK, 1);
    fc2_kernel<<<(BB * 2 + 255) / 256, 256>>>(fc2W, fc2b, (float*)d_out);
}